// round 2
// baseline (speedup 1.0000x reference)
#include <cuda_runtime.h>
#include <cstddef>

// NNUE evaluator, fused single kernel.
// d_in: 0 white_idx [B,32] (int32 or int64 - runtime detected)
//       1 black_idx [B,32]
//       2 w_ft [45056,512] f32   3 b_ft [512]
//       4 w1 [1024,32]           5 b1 [32]
//       6 w2 [32,32]             7 b2 [32]
//       8 w3 [32,1]              9 b3 [1]
// d_out: features [B,1024] f32 followed by values [B] f32.

#define ACC      512
#define NC4      128          // float4 per 512-wide perspective
#define NFEAT    1024
#define NACT     32           // active features per perspective
#define H1       32
#define W1TS     1025         // padded row stride for transposed w1 in smem

// Shared memory layout (floats):
//   feat  : 1024
//   w1T   : 32 * 1025
//   w2s   : 1024
//   b1s   : 32, b2s : 32, w3s : 32, x1s : 32
//   idxs  : 64 ints
#define SMEM_FLOATS (NFEAT + H1 * W1TS + 1024 + 32 + 32 + 32 + 32 + 64)
#define SMEM_BYTES  (SMEM_FLOATS * 4)

__global__ __launch_bounds__(256, 1)
void nnue_fused_kernel(const void* __restrict__ widx_raw,
                       const void* __restrict__ bidx_raw,
                       const float* __restrict__ w_ft,
                       const float* __restrict__ b_ft,
                       const float* __restrict__ w1,
                       const float* __restrict__ b1,
                       const float* __restrict__ w2,
                       const float* __restrict__ b2,
                       const float* __restrict__ w3,
                       const float* __restrict__ b3,
                       float* __restrict__ out_feat,
                       float* __restrict__ out_val,
                       int Bn)
{
    extern __shared__ float smem[];
    float* feat = smem;                       // 1024
    float* w1T  = feat + NFEAT;               // 32 * 1025
    float* w2s  = w1T + H1 * W1TS;            // 1024
    float* b1s  = w2s + 1024;                 // 32
    float* b2s  = b1s + 32;                   // 32
    float* w3s  = b2s + 32;                   // 32
    float* x1s  = w3s + 32;                   // 32
    int*   idxs = (int*)(x1s + 32);           // 64

    const int tid  = threadIdx.x;
    const int lane = tid & 31;
    const int wid  = tid >> 5;

    // ---- one-time per-block staging ----
    // transpose w1 [1024,32] -> w1T[j][i] with padded stride (conflict-free)
    for (int e = tid; e < NFEAT * H1; e += 256) {
        int i = e >> 5;       // feature index
        int j = e & 31;       // output index
        w1T[j * W1TS + i] = w1[e];
    }
    for (int e = tid; e < H1 * H1; e += 256) w2s[e] = w2[e];
    if (tid < 32) {
        b1s[tid] = b1[tid];
        b2s[tid] = b2[tid];
        w3s[tid] = w3[tid];
    }

    // int64 vs int32 index detection: if inputs are int64 (little-endian,
    // values < 2816), the second int32 word is the high half == 0.
    // If int32, the second element is >= 1408 (bucketed offsets), != 0.
    const int is64 = (__ldg((const int*)widx_raw + 1) == 0) ? 1 : 0;
    const float b3v = __ldg(b3);

    const int side = tid >> 7;      // 0 = white, 1 = black
    const int c    = tid & 127;     // float4 column within perspective
    const float4* __restrict__ wft4 = (const float4*)w_ft;
    const float4 bias = ((const float4*)b_ft)[c];

    __syncthreads();

    for (int pos = blockIdx.x; pos < Bn; pos += gridDim.x) {
        // ---- load the 64 active-feature indices (premultiplied by NC4) ----
        if (tid < 64) {
            const void* p = (tid < 32) ? widx_raw : bidx_raw;
            const int a = tid & 31;
            const long long e = (long long)pos * NACT + a;
            int r;
            if (is64) r = (int)((const long long*)p)[e];
            else      r = ((const int*)p)[e];
            idxs[tid] = r * NC4;
        }
        __syncthreads();

        // ---- feature transformer: gather + sum 32 rows (per perspective) ----
        float4 acc = bias;
        const int* __restrict__ my = idxs + side * NACT;
        #pragma unroll
        for (int a0 = 0; a0 < NACT; a0 += 8) {
            float4 v[8];
            #pragma unroll
            for (int a = 0; a < 8; a++)
                v[a] = wft4[my[a0 + a] + c];
            #pragma unroll
            for (int a = 0; a < 8; a++) {
                acc.x += v[a].x; acc.y += v[a].y;
                acc.z += v[a].z; acc.w += v[a].w;
            }
        }
        acc.x = fmaxf(acc.x, 0.f);
        acc.y = fmaxf(acc.y, 0.f);
        acc.z = fmaxf(acc.z, 0.f);
        acc.w = fmaxf(acc.w, 0.f);

        ((float4*)feat)[tid] = acc;   // tid == side*128 + c
        ((float4*)(out_feat + (size_t)pos * NFEAT))[tid] = acc;
        __syncthreads();

        // ---- layer 1: 1024 -> 32, warp w computes outputs 4w..4w+3 ----
        const int j0 = wid * 4;
        const float* __restrict__ r0 = w1T + (j0 + 0) * W1TS;
        const float* __restrict__ r1 = w1T + (j0 + 1) * W1TS;
        const float* __restrict__ r2 = w1T + (j0 + 2) * W1TS;
        const float* __restrict__ r3 = w1T + (j0 + 3) * W1TS;
        float a0 = 0.f, a1 = 0.f, a2 = 0.f, a3 = 0.f;
        #pragma unroll
        for (int k = 0; k < 32; k++) {
            const int i = lane + 32 * k;
            const float f = feat[i];
            a0 = fmaf(f, r0[i], a0);
            a1 = fmaf(f, r1[i], a1);
            a2 = fmaf(f, r2[i], a2);
            a3 = fmaf(f, r3[i], a3);
        }
        #pragma unroll
        for (int o = 16; o; o >>= 1) {
            a0 += __shfl_xor_sync(0xffffffffu, a0, o);
            a1 += __shfl_xor_sync(0xffffffffu, a1, o);
            a2 += __shfl_xor_sync(0xffffffffu, a2, o);
            a3 += __shfl_xor_sync(0xffffffffu, a3, o);
        }
        if (lane == 0) {
            x1s[j0 + 0] = fmaxf(a0 + b1s[j0 + 0], 0.f);
            x1s[j0 + 1] = fmaxf(a1 + b1s[j0 + 1], 0.f);
            x1s[j0 + 2] = fmaxf(a2 + b1s[j0 + 2], 0.f);
            x1s[j0 + 3] = fmaxf(a3 + b1s[j0 + 3], 0.f);
        }
        __syncthreads();

        // ---- layers 2 + 3 (warp 0 only) ----
        if (wid == 0) {
            float s = b2s[lane];
            #pragma unroll
            for (int i = 0; i < H1; i++)
                s = fmaf(x1s[i], w2s[i * H1 + lane], s);
            s = fmaxf(s, 0.f);
            float v = s * w3s[lane];
            #pragma unroll
            for (int o = 16; o; o >>= 1)
                v += __shfl_xor_sync(0xffffffffu, v, o);
            if (lane == 0)
                out_val[pos] = (v + b3v) * 100.0f;
        }
        // no trailing sync needed: the idx-load barrier at the top of the next
        // iteration orders warp 0's layer-2 reads before feat/idxs are rewritten
    }
}

extern "C" void kernel_launch(void* const* d_in, const int* in_sizes, int n_in,
                              void* d_out, int out_size)
{
    (void)n_in; (void)out_size;
    const void*  widx = d_in[0];
    const void*  bidx = d_in[1];
    const float* w_ft = (const float*)d_in[2];
    const float* b_ft = (const float*)d_in[3];
    const float* w1   = (const float*)d_in[4];
    const float* b1   = (const float*)d_in[5];
    const float* w2   = (const float*)d_in[6];
    const float* b2   = (const float*)d_in[7];
    const float* w3   = (const float*)d_in[8];
    const float* b3   = (const float*)d_in[9];

    const int Bn = in_sizes[0] / NACT;    // 4096

    float* out_feat = (float*)d_out;
    float* out_val  = out_feat + (size_t)Bn * NFEAT;

    cudaFuncSetAttribute(nnue_fused_kernel,
                         cudaFuncAttributeMaxDynamicSharedMemorySize,
                         SMEM_BYTES);

    int dev = 0, nsm = 148;
    cudaGetDevice(&dev);
    cudaDeviceGetAttribute(&nsm, cudaDevAttrMultiProcessorCount, dev);
    if (nsm <= 0) nsm = 148;
    int grid = nsm;
    if (grid > Bn) grid = Bn;

    nnue_fused_kernel<<<grid, 256, SMEM_BYTES>>>(
        widx, bidx, w_ft, b_ft, w1, b1, w2, b2, w3, b3,
        out_feat, out_val, Bn);
}

// round 3
// speedup vs baseline: 1.3590x; 1.3590x over previous
#include <cuda_runtime.h>
#include <cstddef>

// NNUE evaluator, fused single kernel, batched P positions per block phase.
// d_in: 0 white_idx [B,32] (int32 or int64 - runtime detected)
//       1 black_idx [B,32]
//       2 w_ft [45056,512] f32   3 b_ft [512]
//       4 w1 [1024,32]           5 b1 [32]
//       6 w2 [32,32]             7 b2 [32]
//       8 w3 [32,1]              9 b3 [1]
// d_out: features [B,1024] f32 followed by values [B] f32.

#define NC4      128          // float4 per 512-wide perspective
#define NFEAT    1024
#define NACT     32
#define H1       32
#define W1TS     1025         // padded row stride for transposed w1 in smem
#define PB       14           // max positions per batch phase
#define X1S      33           // x1s row stride

// smem layout (floats):
//   feat : PB * 1024                      (57344 B)
//   w1T  : 32 * 1025                      (131200 B)
//   w2s  : 1024
//   x1s  : PB * 33
//   b1s/b2s/w3s : 96
//   idxs : PB * 64 ints
#define SMEM_FLOATS (PB*NFEAT + H1*W1TS + 1024 + PB*X1S + 96 + PB*64)
#define SMEM_BYTES  (SMEM_FLOATS * 4)

__global__ __launch_bounds__(256, 1)
void nnue_fused_kernel(const void* __restrict__ widx_raw,
                       const void* __restrict__ bidx_raw,
                       const float* __restrict__ w_ft,
                       const float* __restrict__ b_ft,
                       const float* __restrict__ w1,
                       const float* __restrict__ b1,
                       const float* __restrict__ w2,
                       const float* __restrict__ b2,
                       const float* __restrict__ w3,
                       const float* __restrict__ b3,
                       float* __restrict__ out_feat,
                       float* __restrict__ out_val,
                       int Bn)
{
    extern __shared__ float smem[];
    float* feat = smem;                         // PB*1024
    float* w1T  = feat + PB*NFEAT;              // 32*1025
    float* w2s  = w1T + H1*W1TS;                // 1024
    float* x1s  = w2s + 1024;                   // PB*33
    float* b1s  = x1s + PB*X1S;                 // 32
    float* b2s  = b1s + 32;                     // 32
    float* w3s  = b2s + 32;                     // 32
    int*   idxs = (int*)(w3s + 32);             // PB*64

    const int tid  = threadIdx.x;
    const int lane = tid & 31;
    const int wid  = tid >> 5;

    // ---- one-time staging: transpose w1, copy w2/biases ----
    for (int e = tid; e < NFEAT * H1; e += 256) {
        int i = e >> 5;
        int j = e & 31;
        w1T[j * W1TS + i] = w1[e];
    }
    for (int e = tid; e < H1 * H1; e += 256) w2s[e] = w2[e];
    if (tid < 32) {
        b1s[tid] = b1[tid];
        b2s[tid] = b2[tid];
        w3s[tid] = w3[tid];
    }

    const int is64 = (__ldg((const int*)widx_raw + 1) == 0) ? 1 : 0;
    const float b3v = __ldg(b3);

    const int side = tid >> 7;       // 0 white, 1 black
    const int c    = tid & 127;      // float4 column in perspective
    const float4* __restrict__ wft4 = (const float4*)w_ft;
    const float4 bias = ((const float4*)b_ft)[c];

    // ---- contiguous position range for this block ----
    const int grid = gridDim.x;
    const int base = Bn / grid, rem = Bn % grid;
    const int bid  = blockIdx.x;
    int start, count;
    if (bid < rem) { count = base + 1; start = bid * count; }
    else           { count = base;     start = rem * (base + 1) + (bid - rem) * base; }

    __syncthreads();

    for (int off = 0; off < count; off += PB) {
        const int pos0 = start + off;
        const int npos = (count - off < PB) ? (count - off) : PB;

        // ---- load indices for the batch (premultiplied by NC4) ----
        const int nIdx = npos * 64;
        for (int e = tid; e < nIdx; e += 256) {
            const int p = e >> 6, t = e & 63;
            const void* src = (t < 32) ? widx_raw : bidx_raw;
            const long long g = (long long)(pos0 + p) * NACT + (t & 31);
            int r;
            if (is64) r = (int)((const long long*)src)[g];
            else      r = ((const int*)src)[g];
            idxs[e] = r * NC4;
        }
        __syncthreads();

        // ---- gather: 2 positions interleaved for MLP ----
        for (int p = 0; p < npos; p += 2) {
            const bool has2 = (p + 1 < npos);
            const int* __restrict__ i0 = idxs + p * 64 + side * NACT;
            const int* __restrict__ i1 = has2 ? (idxs + (p + 1) * 64 + side * NACT) : i0;
            float4 a0 = bias, a1 = bias;
            #pragma unroll
            for (int a = 0; a < NACT; a += 4) {
                float4 v0[4], v1[4];
                #pragma unroll
                for (int u = 0; u < 4; u++) v0[u] = wft4[i0[a + u] + c];
                #pragma unroll
                for (int u = 0; u < 4; u++) v1[u] = wft4[i1[a + u] + c];
                #pragma unroll
                for (int u = 0; u < 4; u++) {
                    a0.x += v0[u].x; a0.y += v0[u].y; a0.z += v0[u].z; a0.w += v0[u].w;
                    a1.x += v1[u].x; a1.y += v1[u].y; a1.z += v1[u].z; a1.w += v1[u].w;
                }
            }
            a0.x = fmaxf(a0.x, 0.f); a0.y = fmaxf(a0.y, 0.f);
            a0.z = fmaxf(a0.z, 0.f); a0.w = fmaxf(a0.w, 0.f);
            ((float4*)feat)[p * 256 + tid] = a0;
            ((float4*)(out_feat + (size_t)(pos0 + p) * NFEAT))[tid] = a0;
            if (has2) {
                a1.x = fmaxf(a1.x, 0.f); a1.y = fmaxf(a1.y, 0.f);
                a1.z = fmaxf(a1.z, 0.f); a1.w = fmaxf(a1.w, 0.f);
                ((float4*)feat)[(p + 1) * 256 + tid] = a1;
                ((float4*)(out_feat + (size_t)(pos0 + p + 1) * NFEAT))[tid] = a1;
            }
        }
        __syncthreads();

        // ---- layer 1: [npos x 1024] @ [1024 x 32], warp w owns outputs 4w..4w+3 ----
        {
            const int j0 = wid * 4;
            float acc0[PB], acc1[PB], acc2[PB], acc3[PB];
            #pragma unroll
            for (int p = 0; p < PB; p++) { acc0[p]=0.f; acc1[p]=0.f; acc2[p]=0.f; acc3[p]=0.f; }

            #pragma unroll
            for (int kk = 0; kk < 4; kk++) {          // i-chunks of 256
                float wr0[8], wr1[8], wr2[8], wr3[8];
                #pragma unroll
                for (int k = 0; k < 8; k++) {
                    const int i = lane + 32 * (8 * kk + k);
                    wr0[k] = w1T[(j0 + 0) * W1TS + i];
                    wr1[k] = w1T[(j0 + 1) * W1TS + i];
                    wr2[k] = w1T[(j0 + 2) * W1TS + i];
                    wr3[k] = w1T[(j0 + 3) * W1TS + i];
                }
                #pragma unroll
                for (int p = 0; p < PB; p++) {
                    if (p < npos) {
                        #pragma unroll
                        for (int k = 0; k < 8; k++) {
                            const float f = feat[p * NFEAT + lane + 32 * (8 * kk + k)];
                            acc0[p] = fmaf(f, wr0[k], acc0[p]);
                            acc1[p] = fmaf(f, wr1[k], acc1[p]);
                            acc2[p] = fmaf(f, wr2[k], acc2[p]);
                            acc3[p] = fmaf(f, wr3[k], acc3[p]);
                        }
                    }
                }
            }
            // reduce + write x1
            #pragma unroll
            for (int p = 0; p < PB; p++) {
                if (p < npos) {
                    float s0 = acc0[p], s1 = acc1[p], s2 = acc2[p], s3 = acc3[p];
                    #pragma unroll
                    for (int o = 16; o; o >>= 1) {
                        s0 += __shfl_xor_sync(0xffffffffu, s0, o);
                        s1 += __shfl_xor_sync(0xffffffffu, s1, o);
                        s2 += __shfl_xor_sync(0xffffffffu, s2, o);
                        s3 += __shfl_xor_sync(0xffffffffu, s3, o);
                    }
                    if (lane == 0) {
                        x1s[p * X1S + j0 + 0] = fmaxf(s0 + b1s[j0 + 0], 0.f);
                        x1s[p * X1S + j0 + 1] = fmaxf(s1 + b1s[j0 + 1], 0.f);
                        x1s[p * X1S + j0 + 2] = fmaxf(s2 + b1s[j0 + 2], 0.f);
                        x1s[p * X1S + j0 + 3] = fmaxf(s3 + b1s[j0 + 3], 0.f);
                    }
                }
            }
        }
        __syncthreads();

        // ---- layers 2+3: warp w handles positions w, w+8, ... ----
        for (int p = wid; p < npos; p += 8) {
            float s = b2s[lane];
            #pragma unroll
            for (int i = 0; i < H1; i++)
                s = fmaf(x1s[p * X1S + i], w2s[i * H1 + lane], s);
            s = fmaxf(s, 0.f);
            float v = s * w3s[lane];
            #pragma unroll
            for (int o = 16; o; o >>= 1)
                v += __shfl_xor_sync(0xffffffffu, v, o);
            if (lane == 0)
                out_val[pos0 + p] = (v + b3v) * 100.0f;
        }
        __syncthreads();   // idxs/feat/x1s reuse next batch
    }
}

extern "C" void kernel_launch(void* const* d_in, const int* in_sizes, int n_in,
                              void* d_out, int out_size)
{
    (void)n_in; (void)out_size;
    const void*  widx = d_in[0];
    const void*  bidx = d_in[1];
    const float* w_ft = (const float*)d_in[2];
    const float* b_ft = (const float*)d_in[3];
    const float* w1   = (const float*)d_in[4];
    const float* b1   = (const float*)d_in[5];
    const float* w2   = (const float*)d_in[6];
    const float* b2   = (const float*)d_in[7];
    const float* w3   = (const float*)d_in[8];
    const float* b3   = (const float*)d_in[9];

    const int Bn = in_sizes[0] / NACT;

    float* out_feat = (float*)d_out;
    float* out_val  = out_feat + (size_t)Bn * NFEAT;

    cudaFuncSetAttribute(nnue_fused_kernel,
                         cudaFuncAttributeMaxDynamicSharedMemorySize,
                         SMEM_BYTES);

    int dev = 0, nsm = 148;
    cudaGetDevice(&dev);
    cudaDeviceGetAttribute(&nsm, cudaDevAttrMultiProcessorCount, dev);
    if (nsm <= 0) nsm = 148;
    int grid = nsm;
    if (grid > Bn) grid = Bn;

    nnue_fused_kernel<<<grid, 256, SMEM_BYTES>>>(
        widx, bidx, w_ft, b_ft, w1, b1, w2, b2, w3, b3,
        out_feat, out_val, Bn);
}